// round 13
// baseline (speedup 1.0000x reference)
#include <cuda_runtime.h>
#include <cuda_fp16.h>
#include <math.h>
#include <stdint.h>

// ---------------------------------------------------------------------------
// Problem constants
// ---------------------------------------------------------------------------
#define TOKENS   32768      // 16 * 2048
#define DIM      1024
#define HEADS    8
#define DHEAD    128
#define LN_EPS   1e-5f

// GEMM tiling: CTA 128x128, K-chunk 64, warp tile 64x64, 4 warps (2m x 2n),
// 128 threads, 2 CTAs/SM.  MMA uses fp16 accumulators (2x rate if legacy
// f32-accum HMMA is half-rate), promoted to fp32 masters once per K-chunk.
#define BM       128
#define BN       128
#define BK       64
#define NKK      16           // 1024 / 64 K-chunks
#define STAGES   3
#define SA       144          // smem row stride (128B data + 16B pad)
#define ROWS_PER_STAGE (BM + BN)             // A(128) + B(128) = 256
#define STAGEB   (ROWS_PER_STAGE * SA)       // 36864
#define SMEMB    (STAGES * STAGEB)           // 110592 (x2 CTAs = 216KB/SM)

// Attention: 8 tokens per 256-thread block, one warp per token.
#define ATOK     8
#define AROWS    136                          // padded row stride in halves
#define AWSTRIDE 6912                         // 16B-aligned per-warp region
#define ASMEM    (ATOK * AWSTRIDE)            // 55296

// ---------------------------------------------------------------------------
// Scratch (device globals; cudaMalloc forbidden)
// ---------------------------------------------------------------------------
__device__ __half g_qn  [TOKENS * DIM];
__device__ __half g_kvn [TOKENS * DIM];
__device__ __half g_wq_h [DIM * DIM];
__device__ __half g_wkv_h[2 * DIM * DIM];
__device__ __half g_wo_h [DIM * DIM];
__device__ __half g_query [TOKENS * DIM];
__device__ __half g_kvproj[TOKENS * 2 * DIM];
__device__ __half g_ctx   [TOKENS * DIM];

// ---------------------------------------------------------------------------
// PTX helpers (plain sm_80-level; harness PTX target is sm_103 non-'a')
// ---------------------------------------------------------------------------
__device__ __forceinline__ uint32_t smem_u32(const void* p) {
    uint32_t a;
    asm("{ .reg .u64 t; cvta.to.shared.u64 t, %1; cvt.u32.u64 %0, t; }" : "=r"(a) : "l"(p));
    return a;
}

__device__ __forceinline__ void cp16(uint32_t dst, const void* src) {
    asm volatile("cp.async.cg.shared.global [%0], [%1], 16;" :: "r"(dst), "l"(src));
}
#define CP_COMMIT() asm volatile("cp.async.commit_group;" ::: "memory")
#define CP_WAIT1()  asm volatile("cp.async.wait_group 1;" ::: "memory")

__device__ __forceinline__ void ldsm4(uint32_t* r, uint32_t addr) {
    asm volatile("ldmatrix.sync.aligned.m8n8.x4.shared.b16 {%0,%1,%2,%3}, [%4];"
                 : "=r"(r[0]), "=r"(r[1]), "=r"(r[2]), "=r"(r[3]) : "r"(addr));
}

// fp16-accumulator MMA: D(f16x2 x2) = A(f16) * B(f16) + C(f16)
__device__ __forceinline__ void mma16816hh(uint32_t* d, const uint32_t* a,
                                           uint32_t b0, uint32_t b1) {
    asm volatile("mma.sync.aligned.m16n8k16.row.col.f16.f16.f16.f16 "
                 "{%0,%1}, {%2,%3,%4,%5}, {%6,%7}, {%0,%1};"
                 : "+r"(d[0]), "+r"(d[1])
                 : "r"(a[0]), "r"(a[1]), "r"(a[2]), "r"(a[3]), "r"(b0), "r"(b1));
}

// epilogue store: fp32 or fp16 output
__device__ __forceinline__ void store2(float* p, float a, float b)  { *(float2*)p  = make_float2(a, b); }
__device__ __forceinline__ void store2(__half* p, float a, float b) { *(__half2*)p = __floats2half2_rn(a, b); }

// ---------------------------------------------------------------------------
// Fused LayerNorm (both q and kv) -> fp16.  grid (TOKENS, 2).
// ---------------------------------------------------------------------------
__global__ __launch_bounds__(256)
void ln2_kernel(const float* __restrict__ q,  const float* __restrict__ kv,
                const float* __restrict__ gm, const float* __restrict__ bm,
                const float* __restrict__ gl, const float* __restrict__ bl,
                __half* __restrict__ qn, __half* __restrict__ kvn) {
    const int row = blockIdx.x;
    const int sel = blockIdx.y;
    const float* x     = sel ? kv : q;
    const float* gamma = sel ? gl : gm;
    const float* beta  = sel ? bl : bm;
    __half* y = sel ? kvn : qn;

    const int tid = threadIdx.x;
    float4 v = ((const float4*)(x + (size_t)row * DIM))[tid];

    float s  = v.x + v.y + v.z + v.w;
    float sq = v.x * v.x + v.y * v.y + v.z * v.z + v.w * v.w;
    #pragma unroll
    for (int o = 16; o > 0; o >>= 1) {
        s  += __shfl_xor_sync(0xffffffffu, s,  o);
        sq += __shfl_xor_sync(0xffffffffu, sq, o);
    }
    __shared__ float rs[8], rq[8];
    const int wid = tid >> 5, lane = tid & 31;
    if (lane == 0) { rs[wid] = s; rq[wid] = sq; }
    __syncthreads();
    float tot = 0.f, totq = 0.f;
    #pragma unroll
    for (int i = 0; i < 8; i++) { tot += rs[i]; totq += rq[i]; }

    const float mu   = tot * (1.0f / DIM);
    const float var  = totq * (1.0f / DIM) - mu * mu;
    const float rinv = rsqrtf(var + LN_EPS);

    float4 g = ((const float4*)gamma)[tid];
    float4 b = ((const float4*)beta)[tid];
    float o0 = (v.x - mu) * rinv * g.x + b.x;
    float o1 = (v.y - mu) * rinv * g.y + b.y;
    float o2 = (v.z - mu) * rinv * g.z + b.z;
    float o3 = (v.w - mu) * rinv * g.w + b.w;

    __half2* yp = (__half2*)(y + (size_t)row * DIM);
    yp[2 * tid]     = __floats2half2_rn(o0, o1);
    yp[2 * tid + 1] = __floats2half2_rn(o2, o3);
}

// ---------------------------------------------------------------------------
// All three weights -> fp16 in one launch
// ---------------------------------------------------------------------------
__global__ __launch_bounds__(256)
void wconv_kernel(const float* __restrict__ Wq, const float* __restrict__ Wkv,
                  const float* __restrict__ Wo,
                  __half* __restrict__ wq, __half* __restrict__ wkv, __half* __restrict__ wo) {
    const int i = blockIdx.x * 256 + threadIdx.x;    // 0 .. 4*DIM*DIM-1
    if (i < DIM * DIM)               wq[i]                 = __float2half_rn(Wq[i]);
    else if (i < 3 * DIM * DIM)      wkv[i - DIM * DIM]    = __float2half_rn(Wkv[i - DIM * DIM]);
    else                             wo[i - 3 * DIM * DIM] = __float2half_rn(Wo[i - 3 * DIM * DIM]);
}

// ---------------------------------------------------------------------------
// fp16 GEMM:  C[M,N] = A[M,K] * B[N,K]^T.
// MMA accumulates in fp16 per K-chunk (64), promoted to fp32 masters per chunk.
// CTA 128x128, 4 warps of 64x64 (2m x 2n), 3-stage cp.async, 2 CTAs/SM.
// ---------------------------------------------------------------------------
template <typename OutT>
__global__ __launch_bounds__(128, 2)
void gemm_fp16(const __half* __restrict__ A, const __half* __restrict__ B,
               OutT* __restrict__ C, int ldc) {
    extern __shared__ char smem[];
    const uint32_t sbase = smem_u32(smem);
    const int tid  = threadIdx.x;
    const int wid  = tid >> 5;            // 0..3
    const int lane = tid & 31;
    const int bm = blockIdx.y * BM;
    const int bn = blockIdx.x * BN;
    const int m_base = (wid >> 1) * 64;   // 0 or 64
    const int n_base = (wid & 1) * 64;    // 0 or 64

    float acc[4][8][4];                    // fp32 masters
    #pragma unroll
    for (int i = 0; i < 4; i++)
        #pragma unroll
        for (int j = 0; j < 8; j++)
            #pragma unroll
            for (int k = 0; k < 4; k++) acc[i][j][k] = 0.f;

    // stage loader: 256 rows x 128B, 16B per cp.async, 16 per thread
    auto load_stage = [&](int kk, int s) {
        const uint32_t st = sbase + s * STAGEB;
        #pragma unroll
        for (int i = 0; i < 16; i++) {
            const int idx = tid + i * 128;
            const int row = idx >> 3;          // 0..255
            const int c8  = idx & 7;
            const __half* src = (row < 128)
                ? A + (size_t)(bm + row) * DIM + kk * BK + c8 * 8
                : B + (size_t)(bn + row - 128) * DIM + kk * BK + c8 * 8;
            cp16(st + row * SA + c8 * 16, src);
        }
        CP_COMMIT();
    };

    load_stage(0, 0);
    load_stage(1, 1);

    const int lrow = lane & 15;
    const int lsel = (lane >> 4) * 16;    // 0 or 16 bytes

    for (int kk = 0; kk < NKK; kk++) {
        CP_WAIT1();
        __syncthreads();
        if (kk + 2 < NKK) load_stage(kk + 2, (kk + 2) % STAGES);
        else              CP_COMMIT();     // empty group keeps wait_group 1 sound

        const uint32_t st    = sbase + (kk % STAGES) * STAGEB;
        const uint32_t aaddr = st + (m_base + lrow) * SA + lsel;
        const uint32_t baddr = st + 128 * SA + (n_base + lrow) * SA + lsel;

        // fp16 chunk accumulators (zeroed each K-chunk)
        uint32_t hacc[4][8][2];
        #pragma unroll
        for (int i = 0; i < 4; i++)
            #pragma unroll
            for (int j = 0; j < 8; j++) { hacc[i][j][0] = 0u; hacc[i][j][1] = 0u; }

        #pragma unroll
        for (int ks = 0; ks < 4; ks++) {
            uint32_t br[4][4];
            #pragma unroll
            for (int ni = 0; ni < 4; ni++) ldsm4(br[ni], baddr + ni * 16 * SA + ks * 32);

            uint32_t ar[4][4];
            #pragma unroll
            for (int mi = 0; mi < 4; mi++) ldsm4(ar[mi], aaddr + mi * 16 * SA + ks * 32);

            #pragma unroll
            for (int mi = 0; mi < 4; mi++)
                #pragma unroll
                for (int nj = 0; nj < 8; nj++)
                    mma16816hh(hacc[mi][nj], ar[mi],
                               br[nj >> 1][nj & 1], br[nj >> 1][2 + (nj & 1)]);
        }

        // promote chunk sums to fp32 masters
        #pragma unroll
        for (int mi = 0; mi < 4; mi++)
            #pragma unroll
            for (int nj = 0; nj < 8; nj++) {
                float2 lo = __half22float2(*(const __half2*)&hacc[mi][nj][0]);
                float2 hi = __half22float2(*(const __half2*)&hacc[mi][nj][1]);
                acc[mi][nj][0] += lo.x;  acc[mi][nj][1] += lo.y;
                acc[mi][nj][2] += hi.x;  acc[mi][nj][3] += hi.y;
            }
    }

    // epilogue
    const int g  = lane >> 2;
    const int t2 = (lane & 3) * 2;
    #pragma unroll
    for (int mi = 0; mi < 4; mi++) {
        const int row = bm + m_base + mi * 16 + g;
        OutT* crow = C + (size_t)row * ldc + bn + n_base + t2;
        #pragma unroll
        for (int nj = 0; nj < 8; nj++) {
            store2(crow + nj * 8,                   acc[mi][nj][0], acc[mi][nj][1]);
            store2(crow + (size_t)8 * ldc + nj * 8, acc[mi][nj][2], acc[mi][nj][3]);
        }
    }
}

// ---------------------------------------------------------------------------
// Attention: one warp per token, 8 tokens per 256-thread block. (round-10)
// ---------------------------------------------------------------------------
__global__ __launch_bounds__(256)
void attn_kernel(const __half* __restrict__ query,
                 const __half* __restrict__ kvproj,
                 __half* __restrict__ ctx) {
    extern __shared__ char asmem[];
    const int w    = threadIdx.x >> 5;
    const int lane = threadIdx.x & 31;
    const int t    = blockIdx.x * ATOK + w;

    __half* sq = (__half*)(asmem + w * AWSTRIDE);              // 8 rows x 136
    __half* sk = sq + 8 * AROWS;
    __half* sv = sk + 8 * AROWS;
    float*  sc = (float*)(sv + 8 * AROWS);                     // 64 floats

    {
        const uint4* qp = (const uint4*)(query + (size_t)t * DIM);
        const uint4* kp = (const uint4*)(kvproj + (size_t)t * 2 * DIM);
        const uint4* vp = kp + DIM / 8;
        #pragma unroll
        for (int i = 0; i < 4; i++) {
            const int e4  = i * 32 + lane;        // uint4 index 0..127
            const int row = e4 >> 4;
            const int col = (e4 & 15) * 8;
            *(uint4*)(sq + row * AROWS + col) = qp[e4];
            *(uint4*)(sk + row * AROWS + col) = kp[e4];
            *(uint4*)(sv + row * AROWS + col) = vp[e4];
        }
    }
    __syncwarp();

    #pragma unroll
    for (int pp = 0; pp < 2; pp++) {
        const int p = lane * 2 + pp;
        const int h = p >> 3, g = p & 7;
        const __half2* qq = (const __half2*)(sq + h * AROWS);
        const __half2* kk = (const __half2*)(sk + g * AROWS);
        float s = 0.f;
        #pragma unroll 16
        for (int d2 = 0; d2 < 64; d2++) {
            float2 a = __half22float2(qq[d2]);
            float2 b = __half22float2(kk[d2]);
            s += a.x * b.x + a.y * b.y;
        }
        sc[p] = s * 0.08838834764831845f;   // 1/sqrt(128)
    }
    __syncwarp();

    if (lane < 8) {
        float m = -1e30f;
        #pragma unroll
        for (int g = 0; g < 8; g++) m = fmaxf(m, sc[lane * 8 + g]);
        float e[8], sum = 0.f;
        #pragma unroll
        for (int g = 0; g < 8; g++) { e[g] = expf(sc[lane * 8 + g] - m); sum += e[g]; }
        const float inv = 1.0f / sum;
        #pragma unroll
        for (int g = 0; g < 8; g++) sc[lane * 8 + g] = e[g] * inv;
    }
    __syncwarp();

    #pragma unroll
    for (int j = 0; j < 4; j++) {
        const int d = lane + j * 32;
        #pragma unroll
        for (int h = 0; h < 8; h++) {
            float a = 0.f;
            #pragma unroll
            for (int g = 0; g < 8; g++)
                a += sc[h * 8 + g] * __half2float(sv[g * AROWS + d]);
            ctx[(size_t)t * DIM + h * DHEAD + d] = __float2half_rn(a);
        }
    }
}

// ---------------------------------------------------------------------------
// Host side.  Launch order: ln(0), wconv(1), gemm1(2), gemm2(3), attn(4),
// gemm3(5) -> ncu -s 5 captures gemm3.
// ---------------------------------------------------------------------------
extern "C" void kernel_launch(void* const* d_in, const int* in_sizes, int n_in,
                              void* d_out, int out_size) {
    const float* q       = (const float*)d_in[0];
    const float* kv      = (const float*)d_in[1];
    const float* gamma_m = (const float*)d_in[2];
    const float* beta_m  = (const float*)d_in[3];
    const float* gamma_l = (const float*)d_in[4];
    const float* beta_l  = (const float*)d_in[5];
    const float* Wq      = (const float*)d_in[6];
    const float* Wkv     = (const float*)d_in[7];
    const float* Wo      = (const float*)d_in[8];
    float* out = (float*)d_out;

    void *qn, *kvn, *wq_h, *wkv_h, *wo_h, *query, *kvproj, *ctx;
    cudaGetSymbolAddress(&qn,    g_qn);     cudaGetSymbolAddress(&kvn,   g_kvn);
    cudaGetSymbolAddress(&wq_h,  g_wq_h);   cudaGetSymbolAddress(&wkv_h, g_wkv_h);
    cudaGetSymbolAddress(&wo_h,  g_wo_h);
    cudaGetSymbolAddress(&query, g_query);  cudaGetSymbolAddress(&kvproj, g_kvproj);
    cudaGetSymbolAddress(&ctx,   g_ctx);

    cudaFuncSetAttribute(gemm_fp16<__half>, cudaFuncAttributeMaxDynamicSharedMemorySize, SMEMB);
    cudaFuncSetAttribute(gemm_fp16<float>,  cudaFuncAttributeMaxDynamicSharedMemorySize, SMEMB);
    cudaFuncSetAttribute(attn_kernel,       cudaFuncAttributeMaxDynamicSharedMemorySize, ASMEM);

    // 0: fused LN for q and kv -> fp16
    ln2_kernel<<<dim3(TOKENS, 2), 256>>>(q, kv, gamma_m, beta_m, gamma_l, beta_l,
                                         (__half*)qn, (__half*)kvn);
    // 1: all weights -> fp16
    wconv_kernel<<<(4 * DIM * DIM) / 256, 256>>>(Wq, Wkv, Wo,
                                                 (__half*)wq_h, (__half*)wkv_h, (__half*)wo_h);

    // 2: query = qn @ Wq^T   [32768,1024] (fp16 out)
    gemm_fp16<__half><<<dim3(DIM / BN, TOKENS / BM), 128, SMEMB>>>(
        (const __half*)qn, (const __half*)wq_h, (__half*)query, DIM);
    // 3: kvproj = kvn @ Wkv^T  [32768,2048] (fp16 out)
    gemm_fp16<__half><<<dim3(2 * DIM / BN, TOKENS / BM), 128, SMEMB>>>(
        (const __half*)kvn, (const __half*)wkv_h, (__half*)kvproj, 2 * DIM);

    // 4: attention (warp per token)
    attn_kernel<<<TOKENS / ATOK, 256, ASMEM>>>((const __half*)query,
                                               (const __half*)kvproj, (__half*)ctx);

    // 5: out = ctx @ Wo^T   [32768,1024] (fp32 out)  <- ncu target
    gemm_fp16<float><<<dim3(DIM / BN, TOKENS / BM), 128, SMEMB>>>(
        (const __half*)ctx, (const __half*)wo_h, out, DIM);
}

// round 16
// speedup vs baseline: 1.0791x; 1.0791x over previous
#include <cuda_runtime.h>
#include <cuda_fp16.h>
#include <math.h>
#include <stdint.h>

// ---------------------------------------------------------------------------
// Problem constants
// ---------------------------------------------------------------------------
#define TOKENS   32768      // 16 * 2048
#define DIM      1024
#define HEADS    8
#define DHEAD    128
#define LN_EPS   1e-5f

// GEMM tiling: CTA 128x128, K-chunk 64, warp tile 64x64, 4 warps (2m x 2n),
// 128 threads, 2 CTAs/SM, fp32 accumulators (round-11 proven config).
#define BM       128
#define BN       128
#define BK       64
#define NKK      16           // 1024 / 64 K-chunks
#define STAGES   3
#define SA       144          // smem row stride (128B data + 16B pad)
#define ROWS_PER_STAGE (BM + BN)             // A(128) + B(128) = 256
#define STAGEB   (ROWS_PER_STAGE * SA)       // 36864
#define SMEMB    (STAGES * STAGEB)           // 110592 (x2 CTAs = 216KB/SM)

// Batched QKV launch geometry
#define G1_TX    (DIM / BN)                  // 8
#define G1_TILES (G1_TX * (TOKENS / BM))     // 2048
#define G2_TX    (2 * DIM / BN)              // 16
#define G2_TILES (G2_TX * (TOKENS / BM))     // 4096

// Attention: 8 tokens per 256-thread block, one warp per token.
#define ATOK     8
#define AROWS    136                          // padded row stride in halves
#define AWSTRIDE 6912                         // 16B-aligned per-warp region
#define ASMEM    (ATOK * AWSTRIDE)            // 55296

// ---------------------------------------------------------------------------
// Scratch (device globals; cudaMalloc forbidden)
// ---------------------------------------------------------------------------
__device__ __half g_qn  [TOKENS * DIM];
__device__ __half g_kvn [TOKENS * DIM];
__device__ __half g_wq_h [DIM * DIM];
__device__ __half g_wkv_h[2 * DIM * DIM];
__device__ __half g_wo_h [DIM * DIM];
__device__ __half g_query [TOKENS * DIM];
__device__ __half g_kvproj[TOKENS * 2 * DIM];
__device__ __half g_ctx   [TOKENS * DIM];

// ---------------------------------------------------------------------------
// PTX helpers (plain sm_80-level; harness PTX target is sm_103 non-'a')
// ---------------------------------------------------------------------------
__device__ __forceinline__ uint32_t smem_u32(const void* p) {
    uint32_t a;
    asm("{ .reg .u64 t; cvta.to.shared.u64 t, %1; cvt.u32.u64 %0, t; }" : "=r"(a) : "l"(p));
    return a;
}

__device__ __forceinline__ void cp16(uint32_t dst, const void* src) {
    asm volatile("cp.async.cg.shared.global [%0], [%1], 16;" :: "r"(dst), "l"(src));
}
#define CP_COMMIT() asm volatile("cp.async.commit_group;" ::: "memory")
#define CP_WAIT1()  asm volatile("cp.async.wait_group 1;" ::: "memory")

__device__ __forceinline__ void ldsm4(uint32_t* r, uint32_t addr) {
    asm volatile("ldmatrix.sync.aligned.m8n8.x4.shared.b16 {%0,%1,%2,%3}, [%4];"
                 : "=r"(r[0]), "=r"(r[1]), "=r"(r[2]), "=r"(r[3]) : "r"(addr));
}

__device__ __forceinline__ void mma16816h(float* d, const uint32_t* a, uint32_t b0, uint32_t b1) {
    asm volatile("mma.sync.aligned.m16n8k16.row.col.f32.f16.f16.f32 "
                 "{%0,%1,%2,%3}, {%4,%5,%6,%7}, {%8,%9}, {%0,%1,%2,%3};"
                 : "+f"(d[0]), "+f"(d[1]), "+f"(d[2]), "+f"(d[3])
                 : "r"(a[0]), "r"(a[1]), "r"(a[2]), "r"(a[3]), "r"(b0), "r"(b1));
}

// epilogue store: fp32 or fp16 output
__device__ __forceinline__ void store2(float* p, float a, float b)  { *(float2*)p  = make_float2(a, b); }
__device__ __forceinline__ void store2(__half* p, float a, float b) { *(__half2*)p = __floats2half2_rn(a, b); }

// ---------------------------------------------------------------------------
// Shared GEMM body (round-11 mainloop, fp32 accumulators):
//   C[bm:bm+128, bn:bn+128] = A[bm:,:] * B[bn:,:]^T
// ---------------------------------------------------------------------------
template <typename OutT>
__device__ __forceinline__
void gemm_body(const __half* __restrict__ A, const __half* __restrict__ B,
               OutT* __restrict__ C, int ldc, int bm, int bn, char* smem) {
    const uint32_t sbase = smem_u32(smem);
    const int tid  = threadIdx.x;
    const int wid  = tid >> 5;            // 0..3
    const int lane = tid & 31;
    const int m_base = (wid >> 1) * 64;   // 0 or 64
    const int n_base = (wid & 1) * 64;    // 0 or 64

    float acc[4][8][4];
    #pragma unroll
    for (int i = 0; i < 4; i++)
        #pragma unroll
        for (int j = 0; j < 8; j++)
            #pragma unroll
            for (int k = 0; k < 4; k++) acc[i][j][k] = 0.f;

    // stage loader: 256 rows x 128B, 16B per cp.async, 16 per thread
    auto load_stage = [&](int kk, int s) {
        const uint32_t st = sbase + s * STAGEB;
        #pragma unroll
        for (int i = 0; i < 16; i++) {
            const int idx = tid + i * 128;
            const int row = idx >> 3;          // 0..255
            const int c8  = idx & 7;
            const __half* src = (row < 128)
                ? A + (size_t)(bm + row) * DIM + kk * BK + c8 * 8
                : B + (size_t)(bn + row - 128) * DIM + kk * BK + c8 * 8;
            cp16(st + row * SA + c8 * 16, src);
        }
        CP_COMMIT();
    };

    load_stage(0, 0);
    load_stage(1, 1);

    const int lrow = lane & 15;
    const int lsel = (lane >> 4) * 16;    // 0 or 16 bytes

    for (int kk = 0; kk < NKK; kk++) {
        CP_WAIT1();
        __syncthreads();
        if (kk + 2 < NKK) load_stage(kk + 2, (kk + 2) % STAGES);
        else              CP_COMMIT();     // empty group keeps wait_group 1 sound

        const uint32_t st    = sbase + (kk % STAGES) * STAGEB;
        const uint32_t aaddr = st + (m_base + lrow) * SA + lsel;
        const uint32_t baddr = st + 128 * SA + (n_base + lrow) * SA + lsel;

        #pragma unroll
        for (int ks = 0; ks < 4; ks++) {
            uint32_t br[4][4];
            #pragma unroll
            for (int ni = 0; ni < 4; ni++) ldsm4(br[ni], baddr + ni * 16 * SA + ks * 32);

            uint32_t ar[4][4];
            #pragma unroll
            for (int mi = 0; mi < 4; mi++) ldsm4(ar[mi], aaddr + mi * 16 * SA + ks * 32);

            #pragma unroll
            for (int mi = 0; mi < 4; mi++)
                #pragma unroll
                for (int nj = 0; nj < 8; nj++)
                    mma16816h(acc[mi][nj], ar[mi],
                              br[nj >> 1][nj & 1], br[nj >> 1][2 + (nj & 1)]);
        }
    }

    // epilogue
    const int g  = lane >> 2;
    const int t2 = (lane & 3) * 2;
    #pragma unroll
    for (int mi = 0; mi < 4; mi++) {
        const int row = bm + m_base + mi * 16 + g;
        OutT* crow = C + (size_t)row * ldc + bn + n_base + t2;
        #pragma unroll
        for (int nj = 0; nj < 8; nj++) {
            store2(crow + nj * 8,                   acc[mi][nj][0], acc[mi][nj][1]);
            store2(crow + (size_t)8 * ldc + nj * 8, acc[mi][nj][2], acc[mi][nj][3]);
        }
    }
}

// ---------------------------------------------------------------------------
// Batched Q + KV projection in ONE launch.  Flat grid of 6144 CTAs:
//   bid < 2048  -> query tile   (A=qn,  B=wq,  ldc=DIM)
//   bid >= 2048 -> kvproj tile  (A=kvn, B=wkv, ldc=2*DIM)
// ---------------------------------------------------------------------------
__global__ __launch_bounds__(128, 2)
void gemm_qkv(const __half* __restrict__ qn, const __half* __restrict__ kvn,
              const __half* __restrict__ wq, const __half* __restrict__ wkv,
              __half* __restrict__ query, __half* __restrict__ kvproj) {
    extern __shared__ char smem[];
    const int bid = blockIdx.x;
    if (bid < G1_TILES) {
        const int bx = bid & (G1_TX - 1);
        const int by = bid / G1_TX;
        gemm_body<__half>(qn, wq, query, DIM, by * BM, bx * BN, smem);
    } else {
        const int b2 = bid - G1_TILES;
        const int bx = b2 & (G2_TX - 1);
        const int by = b2 / G2_TX;
        gemm_body<__half>(kvn, wkv, kvproj, 2 * DIM, by * BM, bx * BN, smem);
    }
}

// ---------------------------------------------------------------------------
// Output GEMM (fp32 out)
// ---------------------------------------------------------------------------
__global__ __launch_bounds__(128, 2)
void gemm_out(const __half* __restrict__ A, const __half* __restrict__ B,
              float* __restrict__ C, int ldc) {
    extern __shared__ char smem[];
    gemm_body<float>(A, B, C, ldc, blockIdx.y * BM, blockIdx.x * BN, smem);
}

// ---------------------------------------------------------------------------
// Fused LayerNorm (both q and kv) -> fp16.  grid (TOKENS, 2).
// ---------------------------------------------------------------------------
__global__ __launch_bounds__(256)
void ln2_kernel(const float* __restrict__ q,  const float* __restrict__ kv,
                const float* __restrict__ gm, const float* __restrict__ bm,
                const float* __restrict__ gl, const float* __restrict__ bl,
                __half* __restrict__ qn, __half* __restrict__ kvn) {
    const int row = blockIdx.x;
    const int sel = blockIdx.y;
    const float* x     = sel ? kv : q;
    const float* gamma = sel ? gl : gm;
    const float* beta  = sel ? bl : bm;
    __half* y = sel ? kvn : qn;

    const int tid = threadIdx.x;
    float4 v = ((const float4*)(x + (size_t)row * DIM))[tid];

    float s  = v.x + v.y + v.z + v.w;
    float sq = v.x * v.x + v.y * v.y + v.z * v.z + v.w * v.w;
    #pragma unroll
    for (int o = 16; o > 0; o >>= 1) {
        s  += __shfl_xor_sync(0xffffffffu, s,  o);
        sq += __shfl_xor_sync(0xffffffffu, sq, o);
    }
    __shared__ float rs[8], rq[8];
    const int wid = tid >> 5, lane = tid & 31;
    if (lane == 0) { rs[wid] = s; rq[wid] = sq; }
    __syncthreads();
    float tot = 0.f, totq = 0.f;
    #pragma unroll
    for (int i = 0; i < 8; i++) { tot += rs[i]; totq += rq[i]; }

    const float mu   = tot * (1.0f / DIM);
    const float var  = totq * (1.0f / DIM) - mu * mu;
    const float rinv = rsqrtf(var + LN_EPS);

    float4 g = ((const float4*)gamma)[tid];
    float4 b = ((const float4*)beta)[tid];
    float o0 = (v.x - mu) * rinv * g.x + b.x;
    float o1 = (v.y - mu) * rinv * g.y + b.y;
    float o2 = (v.z - mu) * rinv * g.z + b.z;
    float o3 = (v.w - mu) * rinv * g.w + b.w;

    __half2* yp = (__half2*)(y + (size_t)row * DIM);
    yp[2 * tid]     = __floats2half2_rn(o0, o1);
    yp[2 * tid + 1] = __floats2half2_rn(o2, o3);
}

// ---------------------------------------------------------------------------
// All three weights -> fp16 in one launch
// ---------------------------------------------------------------------------
__global__ __launch_bounds__(256)
void wconv_kernel(const float* __restrict__ Wq, const float* __restrict__ Wkv,
                  const float* __restrict__ Wo,
                  __half* __restrict__ wq, __half* __restrict__ wkv, __half* __restrict__ wo) {
    const int i = blockIdx.x * 256 + threadIdx.x;    // 0 .. 4*DIM*DIM-1
    if (i < DIM * DIM)               wq[i]                 = __float2half_rn(Wq[i]);
    else if (i < 3 * DIM * DIM)      wkv[i - DIM * DIM]    = __float2half_rn(Wkv[i - DIM * DIM]);
    else                             wo[i - 3 * DIM * DIM] = __float2half_rn(Wo[i - 3 * DIM * DIM]);
}

// ---------------------------------------------------------------------------
// Attention: one warp per token, 8 tokens per 256-thread block.
// ---------------------------------------------------------------------------
__global__ __launch_bounds__(256)
void attn_kernel(const __half* __restrict__ query,
                 const __half* __restrict__ kvproj,
                 __half* __restrict__ ctx) {
    extern __shared__ char asmem[];
    const int w    = threadIdx.x >> 5;
    const int lane = threadIdx.x & 31;
    const int t    = blockIdx.x * ATOK + w;

    __half* sq = (__half*)(asmem + w * AWSTRIDE);              // 8 rows x 136
    __half* sk = sq + 8 * AROWS;
    __half* sv = sk + 8 * AROWS;
    float*  sc = (float*)(sv + 8 * AROWS);                     // 64 floats

    {
        const uint4* qp = (const uint4*)(query + (size_t)t * DIM);
        const uint4* kp = (const uint4*)(kvproj + (size_t)t * 2 * DIM);
        const uint4* vp = kp + DIM / 8;
        #pragma unroll
        for (int i = 0; i < 4; i++) {
            const int e4  = i * 32 + lane;        // uint4 index 0..127
            const int row = e4 >> 4;
            const int col = (e4 & 15) * 8;
            *(uint4*)(sq + row * AROWS + col) = qp[e4];
            *(uint4*)(sk + row * AROWS + col) = kp[e4];
            *(uint4*)(sv + row * AROWS + col) = vp[e4];
        }
    }
    __syncwarp();

    #pragma unroll
    for (int pp = 0; pp < 2; pp++) {
        const int p = lane * 2 + pp;
        const int h = p >> 3, g = p & 7;
        const __half2* qq = (const __half2*)(sq + h * AROWS);
        const __half2* kk = (const __half2*)(sk + g * AROWS);
        float s = 0.f;
        #pragma unroll 16
        for (int d2 = 0; d2 < 64; d2++) {
            float2 a = __half22float2(qq[d2]);
            float2 b = __half22float2(kk[d2]);
            s += a.x * b.x + a.y * b.y;
        }
        sc[p] = s * 0.08838834764831845f;   // 1/sqrt(128)
    }
    __syncwarp();

    if (lane < 8) {
        float m = -1e30f;
        #pragma unroll
        for (int g = 0; g < 8; g++) m = fmaxf(m, sc[lane * 8 + g]);
        float e[8], sum = 0.f;
        #pragma unroll
        for (int g = 0; g < 8; g++) { e[g] = expf(sc[lane * 8 + g] - m); sum += e[g]; }
        const float inv = 1.0f / sum;
        #pragma unroll
        for (int g = 0; g < 8; g++) sc[lane * 8 + g] = e[g] * inv;
    }
    __syncwarp();

    #pragma unroll
    for (int j = 0; j < 4; j++) {
        const int d = lane + j * 32;
        #pragma unroll
        for (int h = 0; h < 8; h++) {
            float a = 0.f;
            #pragma unroll
            for (int g = 0; g < 8; g++)
                a += sc[h * 8 + g] * __half2float(sv[g * AROWS + d]);
            ctx[(size_t)t * DIM + h * DHEAD + d] = __float2half_rn(a);
        }
    }
}

// ---------------------------------------------------------------------------
// Host side.  Launch order: ln(0), wconv(1), gemm_qkv(2), attn(3), gemm_out(4)
// ---------------------------------------------------------------------------
extern "C" void kernel_launch(void* const* d_in, const int* in_sizes, int n_in,
                              void* d_out, int out_size) {
    const float* q       = (const float*)d_in[0];
    const float* kv      = (const float*)d_in[1];
    const float* gamma_m = (const float*)d_in[2];
    const float* beta_m  = (const float*)d_in[3];
    const float* gamma_l = (const float*)d_in[4];
    const float* beta_l  = (const float*)d_in[5];
    const float* Wq      = (const float*)d_in[6];
    const float* Wkv     = (const float*)d_in[7];
    const float* Wo      = (const float*)d_in[8];
    float* out = (float*)d_out;

    void *qn, *kvn, *wq_h, *wkv_h, *wo_h, *query, *kvproj, *ctx;
    cudaGetSymbolAddress(&qn,    g_qn);     cudaGetSymbolAddress(&kvn,   g_kvn);
    cudaGetSymbolAddress(&wq_h,  g_wq_h);   cudaGetSymbolAddress(&wkv_h, g_wkv_h);
    cudaGetSymbolAddress(&wo_h,  g_wo_h);
    cudaGetSymbolAddress(&query, g_query);  cudaGetSymbolAddress(&kvproj, g_kvproj);
    cudaGetSymbolAddress(&ctx,   g_ctx);

    cudaFuncSetAttribute(gemm_qkv,    cudaFuncAttributeMaxDynamicSharedMemorySize, SMEMB);
    cudaFuncSetAttribute(gemm_out,    cudaFuncAttributeMaxDynamicSharedMemorySize, SMEMB);
    cudaFuncSetAttribute(attn_kernel, cudaFuncAttributeMaxDynamicSharedMemorySize, ASMEM);

    // 0: fused LN for q and kv -> fp16
    ln2_kernel<<<dim3(TOKENS, 2), 256>>>(q, kv, gamma_m, beta_m, gamma_l, beta_l,
                                         (__half*)qn, (__half*)kvn);
    // 1: all weights -> fp16
    wconv_kernel<<<(4 * DIM * DIM) / 256, 256>>>(Wq, Wkv, Wo,
                                                 (__half*)wq_h, (__half*)wkv_h, (__half*)wo_h);

    // 2: query + kvproj in one batched launch (6144 tiles)
    gemm_qkv<<<G1_TILES + G2_TILES, 128, SMEMB>>>(
        (const __half*)qn, (const __half*)kvn,
        (const __half*)wq_h, (const __half*)wkv_h,
        (__half*)query, (__half*)kvproj);

    // 3: attention (warp per token)
    attn_kernel<<<TOKENS / ATOK, 256, ASMEM>>>((const __half*)query,
                                               (const __half*)kvproj, (__half*)ctx);

    // 4: out = ctx @ Wo^T   [32768,1024] (fp32 out)
    gemm_out<<<dim3(DIM / BN, TOKENS / BM), 128, SMEMB>>>(
        (const __half*)ctx, (const __half*)wo_h, out, DIM);
}

// round 17
// speedup vs baseline: 1.1150x; 1.0333x over previous
#include <cuda_runtime.h>
#include <cuda_fp16.h>
#include <math.h>
#include <stdint.h>

// ---------------------------------------------------------------------------
// Problem constants
// ---------------------------------------------------------------------------
#define TOKENS   32768      // 16 * 2048
#define DIM      1024
#define HEADS    8
#define DHEAD    128
#define LN_EPS   1e-5f

// GEMM tiling: CTA 128x128, K-chunk 64, warp tile 64x64, 4 warps (2m x 2n),
// 128 threads, 2 CTAs/SM, fp32 accumulators (round-11 proven config).
#define BM       128
#define BN       128
#define BK       64
#define NKK      16           // 1024 / 64 K-chunks
#define STAGES   3
#define SA       144          // smem row stride (128B data + 16B pad)
#define ROWS_PER_STAGE (BM + BN)             // A(128) + B(128) = 256
#define STAGEB   (ROWS_PER_STAGE * SA)       // 36864
#define SMEMB    (STAGES * STAGEB)           // 110592 (x2 CTAs = 216KB/SM)

// Batched QKV launch geometry
#define G1_TX    (DIM / BN)                  // 8
#define G1_TILES (G1_TX * (TOKENS / BM))     // 2048
#define G2_TX    (2 * DIM / BN)              // 16
#define G2_TILES (G2_TX * (TOKENS / BM))     // 4096

// Prep kernel geometry: LN warp-per-row + weight conversion, one flat grid
#define LN_BLKS  (2 * TOKENS / 8)            // 8192 (8 rows per 256-thr block)
#define W_ELEMS  (4 * DIM * DIM)             // 4194304 floats total
#define W_BLKS   (W_ELEMS / (256 * 8))       // 2048 (8 floats per thread)

// Attention: 8 tokens per 256-thread block, one warp per token.
#define ATOK     8
#define AROWS    136                          // padded row stride in halves
#define AWSTRIDE 6912                         // 16B-aligned per-warp region
#define ASMEM    (ATOK * AWSTRIDE)            // 55296

// ---------------------------------------------------------------------------
// Scratch (device globals; cudaMalloc forbidden)
// ---------------------------------------------------------------------------
__device__ __half g_qn  [TOKENS * DIM];
__device__ __half g_kvn [TOKENS * DIM];
__device__ __half g_wq_h [DIM * DIM];
__device__ __half g_wkv_h[2 * DIM * DIM];
__device__ __half g_wo_h [DIM * DIM];
__device__ __half g_query [TOKENS * DIM];
__device__ __half g_kvproj[TOKENS * 2 * DIM];
__device__ __half g_ctx   [TOKENS * DIM];

// ---------------------------------------------------------------------------
// PTX helpers (plain sm_80-level; harness PTX target is sm_103 non-'a')
// ---------------------------------------------------------------------------
__device__ __forceinline__ uint32_t smem_u32(const void* p) {
    uint32_t a;
    asm("{ .reg .u64 t; cvta.to.shared.u64 t, %1; cvt.u32.u64 %0, t; }" : "=r"(a) : "l"(p));
    return a;
}

__device__ __forceinline__ void cp16(uint32_t dst, const void* src) {
    asm volatile("cp.async.cg.shared.global [%0], [%1], 16;" :: "r"(dst), "l"(src));
}
#define CP_COMMIT() asm volatile("cp.async.commit_group;" ::: "memory")
#define CP_WAIT1()  asm volatile("cp.async.wait_group 1;" ::: "memory")

__device__ __forceinline__ void ldsm4(uint32_t* r, uint32_t addr) {
    asm volatile("ldmatrix.sync.aligned.m8n8.x4.shared.b16 {%0,%1,%2,%3}, [%4];"
                 : "=r"(r[0]), "=r"(r[1]), "=r"(r[2]), "=r"(r[3]) : "r"(addr));
}

__device__ __forceinline__ void mma16816h(float* d, const uint32_t* a, uint32_t b0, uint32_t b1) {
    asm volatile("mma.sync.aligned.m16n8k16.row.col.f32.f16.f16.f32 "
                 "{%0,%1,%2,%3}, {%4,%5,%6,%7}, {%8,%9}, {%0,%1,%2,%3};"
                 : "+f"(d[0]), "+f"(d[1]), "+f"(d[2]), "+f"(d[3])
                 : "r"(a[0]), "r"(a[1]), "r"(a[2]), "r"(a[3]), "r"(b0), "r"(b1));
}

// epilogue store: fp32 or fp16 output
__device__ __forceinline__ void store2(float* p, float a, float b)  { *(float2*)p  = make_float2(a, b); }
__device__ __forceinline__ void store2(__half* p, float a, float b) { *(__half2*)p = __floats2half2_rn(a, b); }

// ---------------------------------------------------------------------------
// Shared GEMM body (round-11 mainloop, fp32 accumulators)
// ---------------------------------------------------------------------------
template <typename OutT>
__device__ __forceinline__
void gemm_body(const __half* __restrict__ A, const __half* __restrict__ B,
               OutT* __restrict__ C, int ldc, int bm, int bn, char* smem) {
    const uint32_t sbase = smem_u32(smem);
    const int tid  = threadIdx.x;
    const int wid  = tid >> 5;            // 0..3
    const int lane = tid & 31;
    const int m_base = (wid >> 1) * 64;   // 0 or 64
    const int n_base = (wid & 1) * 64;    // 0 or 64

    float acc[4][8][4];
    #pragma unroll
    for (int i = 0; i < 4; i++)
        #pragma unroll
        for (int j = 0; j < 8; j++)
            #pragma unroll
            for (int k = 0; k < 4; k++) acc[i][j][k] = 0.f;

    auto load_stage = [&](int kk, int s) {
        const uint32_t st = sbase + s * STAGEB;
        #pragma unroll
        for (int i = 0; i < 16; i++) {
            const int idx = tid + i * 128;
            const int row = idx >> 3;          // 0..255
            const int c8  = idx & 7;
            const __half* src = (row < 128)
                ? A + (size_t)(bm + row) * DIM + kk * BK + c8 * 8
                : B + (size_t)(bn + row - 128) * DIM + kk * BK + c8 * 8;
            cp16(st + row * SA + c8 * 16, src);
        }
        CP_COMMIT();
    };

    load_stage(0, 0);
    load_stage(1, 1);

    const int lrow = lane & 15;
    const int lsel = (lane >> 4) * 16;    // 0 or 16 bytes

    for (int kk = 0; kk < NKK; kk++) {
        CP_WAIT1();
        __syncthreads();
        if (kk + 2 < NKK) load_stage(kk + 2, (kk + 2) % STAGES);
        else              CP_COMMIT();     // empty group keeps wait_group 1 sound

        const uint32_t st    = sbase + (kk % STAGES) * STAGEB;
        const uint32_t aaddr = st + (m_base + lrow) * SA + lsel;
        const uint32_t baddr = st + 128 * SA + (n_base + lrow) * SA + lsel;

        #pragma unroll
        for (int ks = 0; ks < 4; ks++) {
            uint32_t br[4][4];
            #pragma unroll
            for (int ni = 0; ni < 4; ni++) ldsm4(br[ni], baddr + ni * 16 * SA + ks * 32);

            uint32_t ar[4][4];
            #pragma unroll
            for (int mi = 0; mi < 4; mi++) ldsm4(ar[mi], aaddr + mi * 16 * SA + ks * 32);

            #pragma unroll
            for (int mi = 0; mi < 4; mi++)
                #pragma unroll
                for (int nj = 0; nj < 8; nj++)
                    mma16816h(acc[mi][nj], ar[mi],
                              br[nj >> 1][nj & 1], br[nj >> 1][2 + (nj & 1)]);
        }
    }

    const int g  = lane >> 2;
    const int t2 = (lane & 3) * 2;
    #pragma unroll
    for (int mi = 0; mi < 4; mi++) {
        const int row = bm + m_base + mi * 16 + g;
        OutT* crow = C + (size_t)row * ldc + bn + n_base + t2;
        #pragma unroll
        for (int nj = 0; nj < 8; nj++) {
            store2(crow + nj * 8,                   acc[mi][nj][0], acc[mi][nj][1]);
            store2(crow + (size_t)8 * ldc + nj * 8, acc[mi][nj][2], acc[mi][nj][3]);
        }
    }
}

// ---------------------------------------------------------------------------
// Batched Q + KV projection in ONE launch (6144 CTAs).
// ---------------------------------------------------------------------------
__global__ __launch_bounds__(128, 2)
void gemm_qkv(const __half* __restrict__ qn, const __half* __restrict__ kvn,
              const __half* __restrict__ wq, const __half* __restrict__ wkv,
              __half* __restrict__ query, __half* __restrict__ kvproj) {
    extern __shared__ char smem[];
    const int bid = blockIdx.x;
    if (bid < G1_TILES) {
        const int bx = bid & (G1_TX - 1);
        const int by = bid / G1_TX;
        gemm_body<__half>(qn, wq, query, DIM, by * BM, bx * BN, smem);
    } else {
        const int b2 = bid - G1_TILES;
        const int bx = b2 & (G2_TX - 1);
        const int by = b2 / G2_TX;
        gemm_body<__half>(kvn, wkv, kvproj, 2 * DIM, by * BM, bx * BN, smem);
    }
}

// ---------------------------------------------------------------------------
// Output GEMM (fp32 out)
// ---------------------------------------------------------------------------
__global__ __launch_bounds__(128, 2)
void gemm_out(const __half* __restrict__ A, const __half* __restrict__ B,
              float* __restrict__ C, int ldc) {
    extern __shared__ char smem[];
    gemm_body<float>(A, B, C, ldc, blockIdx.y * BM, blockIdx.x * BN, smem);
}

// ---------------------------------------------------------------------------
// Prep kernel: warp-per-row LayerNorm (blocks < LN_BLKS) + weight->fp16
// conversion (blocks >= LN_BLKS).  No block barriers anywhere.
// ---------------------------------------------------------------------------
__global__ __launch_bounds__(256)
void prep_kernel(const float* __restrict__ q,  const float* __restrict__ kv,
                 const float* __restrict__ gm, const float* __restrict__ bm,
                 const float* __restrict__ gl, const float* __restrict__ bl,
                 const float* __restrict__ Wq, const float* __restrict__ Wkv,
                 const float* __restrict__ Wo,
                 __half* __restrict__ qn, __half* __restrict__ kvn,
                 __half* __restrict__ wq, __half* __restrict__ wkv,
                 __half* __restrict__ wo) {
    const int blk = blockIdx.x;
    if (blk < LN_BLKS) {
        // ---- LayerNorm: one warp per row, 8 rows per block ----
        const int w    = threadIdx.x >> 5;
        const int lane = threadIdx.x & 31;
        const int r    = blk * 8 + w;           // 0 .. 65535
        const float* x;
        const float* gamma;
        const float* beta;
        __half* y;
        int row;
        if (r < TOKENS) { x = q;  gamma = gm; beta = bm; y = qn;  row = r; }
        else            { x = kv; gamma = gl; beta = bl; y = kvn; row = r - TOKENS; }

        const float4* xr = (const float4*)(x + (size_t)row * DIM);
        float4 v[8];
        float s = 0.f, sq = 0.f;
        #pragma unroll
        for (int i = 0; i < 8; i++) {
            v[i] = xr[lane + 32 * i];
            s  += v[i].x + v[i].y + v[i].z + v[i].w;
            sq += v[i].x * v[i].x + v[i].y * v[i].y + v[i].z * v[i].z + v[i].w * v[i].w;
        }
        #pragma unroll
        for (int o = 16; o > 0; o >>= 1) {
            s  += __shfl_xor_sync(0xffffffffu, s,  o);
            sq += __shfl_xor_sync(0xffffffffu, sq, o);
        }
        const float mu   = s * (1.0f / DIM);
        const float var  = sq * (1.0f / DIM) - mu * mu;
        const float rinv = rsqrtf(var + LN_EPS);

        __half2* yp = (__half2*)(y + (size_t)row * DIM);
        #pragma unroll
        for (int i = 0; i < 8; i++) {
            const int e4 = lane + 32 * i;
            float4 g = ((const float4*)gamma)[e4];
            float4 b = ((const float4*)beta)[e4];
            float o0 = (v[i].x - mu) * rinv * g.x + b.x;
            float o1 = (v[i].y - mu) * rinv * g.y + b.y;
            float o2 = (v[i].z - mu) * rinv * g.z + b.z;
            float o3 = (v[i].w - mu) * rinv * g.w + b.w;
            yp[2 * e4]     = __floats2half2_rn(o0, o1);
            yp[2 * e4 + 1] = __floats2half2_rn(o2, o3);
        }
    } else {
        // ---- weight conversion: 8 floats per thread ----
        const size_t base = (size_t)(blk - LN_BLKS) * (256 * 8) + (size_t)threadIdx.x * 8;
        const float* src;
        __half* dst;
        size_t off;
        if (base < (size_t)DIM * DIM)            { src = Wq;  dst = wq;  off = base; }
        else if (base < (size_t)3 * DIM * DIM)   { src = Wkv; dst = wkv; off = base - (size_t)DIM * DIM; }
        else                                     { src = Wo;  dst = wo;  off = base - (size_t)3 * DIM * DIM; }
        float4 a = ((const float4*)(src + off))[0];
        float4 b = ((const float4*)(src + off))[1];
        __half2* dp = (__half2*)(dst + off);
        dp[0] = __floats2half2_rn(a.x, a.y);
        dp[1] = __floats2half2_rn(a.z, a.w);
        dp[2] = __floats2half2_rn(b.x, b.y);
        dp[3] = __floats2half2_rn(b.z, b.w);
    }
}

// ---------------------------------------------------------------------------
// Attention: one warp per token, 8 tokens per 256-thread block.
// ---------------------------------------------------------------------------
__global__ __launch_bounds__(256)
void attn_kernel(const __half* __restrict__ query,
                 const __half* __restrict__ kvproj,
                 __half* __restrict__ ctx) {
    extern __shared__ char asmem[];
    const int w    = threadIdx.x >> 5;
    const int lane = threadIdx.x & 31;
    const int t    = blockIdx.x * ATOK + w;

    __half* sq = (__half*)(asmem + w * AWSTRIDE);              // 8 rows x 136
    __half* sk = sq + 8 * AROWS;
    __half* sv = sk + 8 * AROWS;
    float*  sc = (float*)(sv + 8 * AROWS);                     // 64 floats

    {
        const uint4* qp = (const uint4*)(query + (size_t)t * DIM);
        const uint4* kp = (const uint4*)(kvproj + (size_t)t * 2 * DIM);
        const uint4* vp = kp + DIM / 8;
        #pragma unroll
        for (int i = 0; i < 4; i++) {
            const int e4  = i * 32 + lane;        // uint4 index 0..127
            const int row = e4 >> 4;
            const int col = (e4 & 15) * 8;
            *(uint4*)(sq + row * AROWS + col) = qp[e4];
            *(uint4*)(sk + row * AROWS + col) = kp[e4];
            *(uint4*)(sv + row * AROWS + col) = vp[e4];
        }
    }
    __syncwarp();

    #pragma unroll
    for (int pp = 0; pp < 2; pp++) {
        const int p = lane * 2 + pp;
        const int h = p >> 3, g = p & 7;
        const __half2* qq = (const __half2*)(sq + h * AROWS);
        const __half2* kk = (const __half2*)(sk + g * AROWS);
        float s = 0.f;
        #pragma unroll 16
        for (int d2 = 0; d2 < 64; d2++) {
            float2 a = __half22float2(qq[d2]);
            float2 b = __half22float2(kk[d2]);
            s += a.x * b.x + a.y * b.y;
        }
        sc[p] = s * 0.08838834764831845f;   // 1/sqrt(128)
    }
    __syncwarp();

    if (lane < 8) {
        float m = -1e30f;
        #pragma unroll
        for (int g = 0; g < 8; g++) m = fmaxf(m, sc[lane * 8 + g]);
        float e[8], sum = 0.f;
        #pragma unroll
        for (int g = 0; g < 8; g++) { e[g] = expf(sc[lane * 8 + g] - m); sum += e[g]; }
        const float inv = 1.0f / sum;
        #pragma unroll
        for (int g = 0; g < 8; g++) sc[lane * 8 + g] = e[g] * inv;
    }
    __syncwarp();

    #pragma unroll
    for (int j = 0; j < 4; j++) {
        const int d = lane + j * 32;
        #pragma unroll
        for (int h = 0; h < 8; h++) {
            float a = 0.f;
            #pragma unroll
            for (int g = 0; g < 8; g++)
                a += sc[h * 8 + g] * __half2float(sv[g * AROWS + d]);
            ctx[(size_t)t * DIM + h * DHEAD + d] = __float2half_rn(a);
        }
    }
}

// ---------------------------------------------------------------------------
// Host side.  Launch order: prep(0), gemm_qkv(1), attn(2), gemm_out(3)
// ---------------------------------------------------------------------------
extern "C" void kernel_launch(void* const* d_in, const int* in_sizes, int n_in,
                              void* d_out, int out_size) {
    const float* q       = (const float*)d_in[0];
    const float* kv      = (const float*)d_in[1];
    const float* gamma_m = (const float*)d_in[2];
    const float* beta_m  = (const float*)d_in[3];
    const float* gamma_l = (const float*)d_in[4];
    const float* beta_l  = (const float*)d_in[5];
    const float* Wq      = (const float*)d_in[6];
    const float* Wkv     = (const float*)d_in[7];
    const float* Wo      = (const float*)d_in[8];
    float* out = (float*)d_out;

    void *qn, *kvn, *wq_h, *wkv_h, *wo_h, *query, *kvproj, *ctx;
    cudaGetSymbolAddress(&qn,    g_qn);     cudaGetSymbolAddress(&kvn,   g_kvn);
    cudaGetSymbolAddress(&wq_h,  g_wq_h);   cudaGetSymbolAddress(&wkv_h, g_wkv_h);
    cudaGetSymbolAddress(&wo_h,  g_wo_h);
    cudaGetSymbolAddress(&query, g_query);  cudaGetSymbolAddress(&kvproj, g_kvproj);
    cudaGetSymbolAddress(&ctx,   g_ctx);

    cudaFuncSetAttribute(gemm_qkv,    cudaFuncAttributeMaxDynamicSharedMemorySize, SMEMB);
    cudaFuncSetAttribute(gemm_out,    cudaFuncAttributeMaxDynamicSharedMemorySize, SMEMB);
    cudaFuncSetAttribute(attn_kernel, cudaFuncAttributeMaxDynamicSharedMemorySize, ASMEM);

    // 0: fused prep (LN warp-per-row + weight conversion)
    prep_kernel<<<LN_BLKS + W_BLKS, 256>>>(q, kv, gamma_m, beta_m, gamma_l, beta_l,
                                           Wq, Wkv, Wo,
                                           (__half*)qn, (__half*)kvn,
                                           (__half*)wq_h, (__half*)wkv_h, (__half*)wo_h);

    // 1: query + kvproj in one batched launch (6144 tiles)
    gemm_qkv<<<G1_TILES + G2_TILES, 128, SMEMB>>>(
        (const __half*)qn, (const __half*)kvn,
        (const __half*)wq_h, (const __half*)wkv_h,
        (__half*)query, (__half*)kvproj);

    // 2: attention (warp per token)
    attn_kernel<<<TOKENS / ATOK, 256, ASMEM>>>((const __half*)query,
                                               (const __half*)kvproj, (__half*)ctx);

    // 3: out = ctx @ Wo^T   [32768,1024] (fp32 out)
    gemm_out<<<dim3(DIM / BN, TOKENS / BM), 128, SMEMB>>>(
        (const __half*)ctx, (const __half*)wo_h, out, DIM);
}